// round 2
// baseline (speedup 1.0000x reference)
#include <cuda_runtime.h>

#define NN 384
#define DD 128
#define MARGIN_F 0.2f
#define APB 4               // anchors per block
#define NBLK (NN / APB)     // 96 blocks
#define NTHR 256

__device__ float g_total;
__device__ float g_count;
__device__ unsigned int g_ctr;

__global__ void __launch_bounds__(NTHR, 4) triplet_fused_k(
    const float* __restrict__ feat,
    const int*   __restrict__ y,
    float*       __restrict__ out)
{
    const int t = threadIdx.x;
    const int a0 = blockIdx.x * APB;

    __shared__ float fa[APB][DD];        // anchor feature rows
    __shared__ float drow[APB][NN];      // d2 rows for the 4 anchors
    __shared__ int   ys[NN];             // labels
    __shared__ float pos_d[NN];          // compacted positive distances (+margin)
    __shared__ int   npos_s;
    __shared__ float red_f[NTHR / 32];

    // ---- stage labels + anchor rows ----
    for (int j = t; j < NN; j += NTHR) ys[j] = y[j];
#pragma unroll
    for (int m = 0; m < APB; m++) {
        for (int k = t; k < DD; k += NTHR) fa[m][k] = feat[(a0 + m) * DD + k];
    }
    __syncthreads();

    // ---- distance phase: each thread computes d2[a0+m][j] for its j's ----
    for (int j = t; j < NN; j += NTHR) {
        const float4* fj = reinterpret_cast<const float4*>(feat + j * DD);
        float acc0 = 0.f, acc1 = 0.f, acc2 = 0.f, acc3 = 0.f;
#pragma unroll
        for (int k = 0; k < DD / 4; k++) {
            float4 v = fj[k];
            float d;
            d = fa[0][4*k+0] - v.x; acc0 += d * d;
            d = fa[0][4*k+1] - v.y; acc0 += d * d;
            d = fa[0][4*k+2] - v.z; acc0 += d * d;
            d = fa[0][4*k+3] - v.w; acc0 += d * d;
            d = fa[1][4*k+0] - v.x; acc1 += d * d;
            d = fa[1][4*k+1] - v.y; acc1 += d * d;
            d = fa[1][4*k+2] - v.z; acc1 += d * d;
            d = fa[1][4*k+3] - v.w; acc1 += d * d;
            d = fa[2][4*k+0] - v.x; acc2 += d * d;
            d = fa[2][4*k+1] - v.y; acc2 += d * d;
            d = fa[2][4*k+2] - v.z; acc2 += d * d;
            d = fa[2][4*k+3] - v.w; acc2 += d * d;
            d = fa[3][4*k+0] - v.x; acc3 += d * d;
            d = fa[3][4*k+1] - v.y; acc3 += d * d;
            d = fa[3][4*k+2] - v.z; acc3 += d * d;
            d = fa[3][4*k+3] - v.w; acc3 += d * d;
        }
        drow[0][j] = acc0;
        drow[1][j] = acc1;
        drow[2][j] = acc2;
        drow[3][j] = acc3;
    }
    __syncthreads();

    // ---- triplet phase ----
    float acc = 0.0f;     // per-thread partial of total
    int   cnt = 0;        // per-thread partial of count (only thread 0 adds)

#pragma unroll 1
    for (int m = 0; m < APB; m++) {
        const int a  = a0 + m;
        const int ya = ys[a];

        if (t == 0) npos_s = 0;
        __syncthreads();

        // compact positives: pos_d[i] = d2[a][p] + margin
        for (int p = t; p < NN; p += NTHR) {
            if (ys[p] == ya && p != a) {
                int idx = atomicAdd(&npos_s, 1);
                pos_d[idx] = drow[m][p] + MARGIN_F;
            }
        }
        __syncthreads();

        const int np = npos_s;
        if (t == 0) cnt += np * (NN - 1 - np);   // nneg = NN - (np+1)

        if (np > 0) {
            for (int n = t; n < NN; n += NTHR) {
                if (ys[n] != ya) {
                    const float dn = drow[m][n];
                    for (int i = 0; i < np; i++) {
                        float v = pos_d[i] - dn;
                        acc += (v > 0.0f) ? v : 0.0f;
                    }
                }
            }
        }
        __syncthreads();  // protect npos_s / pos_d reuse
    }

    // ---- block reduction of acc ----
    const unsigned FULL = 0xFFFFFFFFu;
#pragma unroll
    for (int off = 16; off > 0; off >>= 1)
        acc += __shfl_down_sync(FULL, acc, off);
    const int warp = t >> 5, lane = t & 31;
    if (lane == 0) red_f[warp] = acc;
    __syncthreads();
    if (warp == 0) {
        float af = (lane < NTHR / 32) ? red_f[lane] : 0.0f;
#pragma unroll
        for (int off = 4; off > 0; off >>= 1)
            af += __shfl_down_sync(FULL, af, off);
        if (lane == 0) {
            atomicAdd(&g_total, af);
            atomicAdd(&g_count, (float)cnt);
            __threadfence();
            unsigned done = atomicAdd(&g_ctr, 1u);
            if (done == NBLK - 1) {
                // last block: finalize and reset for next graph replay
                float tot = atomicAdd(&g_total, 0.0f);
                float cn  = atomicAdd(&g_count, 0.0f);
                out[0] = tot / cn;
                g_total = 0.0f;
                g_count = 0.0f;
                g_ctr   = 0u;
            }
        }
    }
}

extern "C" void kernel_launch(void* const* d_in, const int* in_sizes, int n_in,
                              void* d_out, int out_size) {
    const float* feat = (const float*)d_in[0];
    // d_in[1] = logits (unused by the loss)
    const int*   yv   = (const int*)d_in[2];
    float* out = (float*)d_out;

    triplet_fused_k<<<NBLK, NTHR>>>(feat, yv, out);
}

// round 3
// speedup vs baseline: 1.2106x; 1.2106x over previous
#include <cuda_runtime.h>

#define NN 384
#define DD 128
#define MARGIN_F 0.2f
#define APB 4               // anchors per block
#define NBLK (NN / APB)     // 96 blocks
#define NTHR 256
#define PBLK 48             // prep blocks (8 rows each)

// Scratch (no allocations allowed)
__device__ float g_featT[DD * NN];   // transposed features [k][j]
__device__ float g_r[NN];            // squared norms
__device__ float g_total;
__device__ float g_count;
__device__ unsigned int g_ctr;

// Transpose feat -> g_featT and compute row norms. One warp per row.
__global__ void __launch_bounds__(NTHR) prep_k(const float* __restrict__ feat) {
    const int warp = threadIdx.x >> 5;
    const int lane = threadIdx.x & 31;
    const int j = blockIdx.x * 8 + warp;   // row index

    // coalesced float4 load of row j
    const float4 v = reinterpret_cast<const float4*>(feat + j * DD)[lane];

    // transpose stores (scattered; fire-and-forget)
    g_featT[(lane * 4 + 0) * NN + j] = v.x;
    g_featT[(lane * 4 + 1) * NN + j] = v.y;
    g_featT[(lane * 4 + 2) * NN + j] = v.z;
    g_featT[(lane * 4 + 3) * NN + j] = v.w;

    // squared norm via warp reduction
    float s = v.x * v.x + v.y * v.y + v.z * v.z + v.w * v.w;
    const unsigned FULL = 0xFFFFFFFFu;
#pragma unroll
    for (int off = 16; off > 0; off >>= 1)
        s += __shfl_down_sync(FULL, s, off);
    if (lane == 0) g_r[j] = s;
}

__global__ void __launch_bounds__(NTHR) main_k(
    const float* __restrict__ feat,
    const int*   __restrict__ y,
    float*       __restrict__ out)
{
    const int t = threadIdx.x;
    const int a0 = blockIdx.x * APB;

    __shared__ float4 fa4[APB][DD / 4];  // anchor rows, float4 for LDS.128 broadcast
    __shared__ float drow[APB][NN];      // d2 rows for the 4 anchors
    __shared__ float ra[APB];            // anchor norms
    __shared__ int   ys[NN];             // labels
    __shared__ float pos_d[64];          // compacted positive distances (+margin)
    __shared__ int   npos_s;
    __shared__ float red_f[NTHR / 32];

    // ---- stage labels + anchor rows ----
    for (int j = t; j < NN; j += NTHR) ys[j] = y[j];
    if (t < APB * (DD / 4)) {
        const int m = t / (DD / 4);
        const int k4 = t % (DD / 4);
        fa4[m][k4] = reinterpret_cast<const float4*>(feat + (a0 + m) * DD)[k4];
    }
    if (t < APB) ra[t] = g_r[a0 + t];
    __syncthreads();

    // ---- distance phase: dot-form, coalesced feat_T reads ----
    for (int j = t; j < NN; j += NTHR) {
        float acc0 = 0.f, acc1 = 0.f, acc2 = 0.f, acc3 = 0.f;
#pragma unroll 8
        for (int k4 = 0; k4 < DD / 4; k4++) {
            const float v0 = g_featT[(4 * k4 + 0) * NN + j];
            const float v1 = g_featT[(4 * k4 + 1) * NN + j];
            const float v2 = g_featT[(4 * k4 + 2) * NN + j];
            const float v3 = g_featT[(4 * k4 + 3) * NN + j];
            float4 a;
            a = fa4[0][k4];
            acc0 += a.x * v0 + a.y * v1 + a.z * v2 + a.w * v3;
            a = fa4[1][k4];
            acc1 += a.x * v0 + a.y * v1 + a.z * v2 + a.w * v3;
            a = fa4[2][k4];
            acc2 += a.x * v0 + a.y * v1 + a.z * v2 + a.w * v3;
            a = fa4[3][k4];
            acc3 += a.x * v0 + a.y * v1 + a.z * v2 + a.w * v3;
        }
        const float rj = g_r[j];
        drow[0][j] = fmaxf(ra[0] + rj - 2.0f * acc0, 0.0f);
        drow[1][j] = fmaxf(ra[1] + rj - 2.0f * acc1, 0.0f);
        drow[2][j] = fmaxf(ra[2] + rj - 2.0f * acc2, 0.0f);
        drow[3][j] = fmaxf(ra[3] + rj - 2.0f * acc3, 0.0f);
    }
    __syncthreads();

    // ---- triplet phase ----
    float acc = 0.0f;     // per-thread partial of total
    int   cnt = 0;        // per-block count (thread 0 only)

#pragma unroll 1
    for (int m = 0; m < APB; m++) {
        const int a  = a0 + m;
        const int ya = ys[a];

        if (t == 0) npos_s = 0;
        __syncthreads();

        // compact positives: pos_d[i] = d2[a][p] + margin
        for (int p = t; p < NN; p += NTHR) {
            if (ys[p] == ya && p != a) {
                int idx = atomicAdd(&npos_s, 1);
                pos_d[idx] = drow[m][p] + MARGIN_F;
            }
        }
        __syncthreads();

        const int np = npos_s;
        if (t == 0) cnt += np * (NN - 1 - np);

        if (np > 0) {
            for (int n = t; n < NN; n += NTHR) {
                if (ys[n] != ya) {
                    const float dn = drow[m][n];
                    for (int i = 0; i < np; i++) {
                        float v = pos_d[i] - dn;
                        acc += (v > 0.0f) ? v : 0.0f;
                    }
                }
            }
        }
        __syncthreads();  // protect npos_s / pos_d reuse
    }

    // ---- block reduction + global accumulate + last-block finalize ----
    const unsigned FULL = 0xFFFFFFFFu;
#pragma unroll
    for (int off = 16; off > 0; off >>= 1)
        acc += __shfl_down_sync(FULL, acc, off);
    const int warp = t >> 5, lane = t & 31;
    if (lane == 0) red_f[warp] = acc;
    __syncthreads();
    if (warp == 0) {
        float af = (lane < NTHR / 32) ? red_f[lane] : 0.0f;
#pragma unroll
        for (int off = 4; off > 0; off >>= 1)
            af += __shfl_down_sync(FULL, af, off);
        if (lane == 0) {
            atomicAdd(&g_total, af);
            atomicAdd(&g_count, (float)cnt);
            __threadfence();
            unsigned done = atomicAdd(&g_ctr, 1u);
            if (done == NBLK - 1) {
                float tot = atomicAdd(&g_total, 0.0f);
                float cn  = atomicAdd(&g_count, 0.0f);
                out[0] = tot / cn;
                g_total = 0.0f;
                g_count = 0.0f;
                g_ctr   = 0u;
            }
        }
    }
}

extern "C" void kernel_launch(void* const* d_in, const int* in_sizes, int n_in,
                              void* d_out, int out_size) {
    const float* feat = (const float*)d_in[0];
    // d_in[1] = logits (unused by the loss)
    const int*   yv   = (const int*)d_in[2];
    float* out = (float*)d_out;

    prep_k<<<PBLK, NTHR>>>(feat);
    main_k<<<NBLK, NTHR>>>(feat, yv, out);
}

// round 4
// speedup vs baseline: 2.1054x; 1.7391x over previous
#include <cuda_runtime.h>

#define NN 384
#define DD 128
#define MARGIN_F 0.2f
#define APB 3               // anchors per block
#define NBLK (NN / APB)     // 128 blocks -> single wave on 148 SMs
#define NTHR NN             // 384 threads: one column j per thread
#define SMPAD 132           // padded row stride (floats) for transpose tile

// Scratch (no allocations allowed)
__device__ float4 g_featT4[(DD / 4) * NN];  // [k4][j] packed transpose
__device__ float  g_r[NN];                  // squared norms
__device__ float  g_total;
__device__ float  g_count;
__device__ unsigned int g_ctr;

// ---- prep: smem-tiled transpose (32 rows per block) + row norms ----
__global__ void __launch_bounds__(256) prep_k(const float* __restrict__ feat) {
    __shared__ float tile[32][SMPAD];
    const int t = threadIdx.x;
    const int j0 = blockIdx.x * 32;
    const unsigned FULL = 0xFFFFFFFFu;

    // load 32 rows x 128 cols, coalesced; 8 threads per row, 4 float4 each
    const int row = t >> 3;          // 0..31
    const int f4b = (t & 7) * 4;     // float4 base within row
    const float4* src = reinterpret_cast<const float4*>(feat + (j0 + row) * DD);
    float ss = 0.0f;
#pragma unroll
    for (int i = 0; i < 4; i++) {
        float4 v = src[f4b + i];
        *reinterpret_cast<float4*>(&tile[row][(f4b + i) * 4]) = v;
        ss += v.x * v.x + v.y * v.y + v.z * v.z + v.w * v.w;
    }
    // reduce norm over the 8 threads of this row (same warp, width 8)
    ss += __shfl_down_sync(FULL, ss, 4, 8);
    ss += __shfl_down_sync(FULL, ss, 2, 8);
    ss += __shfl_down_sync(FULL, ss, 1, 8);
    if ((t & 7) == 0) g_r[j0 + row] = ss;
    __syncthreads();

    // store transposed: warp w handles k4 = rep*8 + w, lanes = consecutive j
    const int w = t >> 5;
    const int lane = t & 31;
#pragma unroll
    for (int rep = 0; rep < 4; rep++) {
        const int k4 = rep * 8 + w;
        float4 v = *reinterpret_cast<const float4*>(&tile[lane][k4 * 4]);
        g_featT4[k4 * NN + j0 + lane] = v;
    }
}

// ---- fused distance + triplet kernel ----
__global__ void __launch_bounds__(NTHR) main_k(
    const float* __restrict__ feat,
    const int*   __restrict__ y,
    float*       __restrict__ out)
{
    const int t = threadIdx.x;       // == column j
    const int a0 = blockIdx.x * APB;

    __shared__ float4 fa4[APB][DD / 4];
    __shared__ float  drow[APB][NN];
    __shared__ float  ra[APB];
    __shared__ int    ys[NN];
    __shared__ float  pos_d[NN];
    __shared__ int    npos_s;
    __shared__ float  red_f[NTHR / 32];

    ys[t] = y[t];
    if (t < APB * (DD / 4)) {
        const int m = t / (DD / 4);
        const int k4 = t % (DD / 4);
        fa4[m][k4] = reinterpret_cast<const float4*>(feat + (a0 + m) * DD)[k4];
    }
    if (t < APB) ra[t] = g_r[a0 + t];
    __syncthreads();

    // distance phase: thread t computes d2[a0+m][t] for m = 0..2
    {
        float acc0 = 0.f, acc1 = 0.f, acc2 = 0.f;
#pragma unroll 8
        for (int k4 = 0; k4 < DD / 4; k4++) {
            const float4 v = g_featT4[k4 * NN + t];
            float4 A;
            A = fa4[0][k4];
            acc0 += A.x * v.x; acc0 += A.y * v.y; acc0 += A.z * v.z; acc0 += A.w * v.w;
            A = fa4[1][k4];
            acc1 += A.x * v.x; acc1 += A.y * v.y; acc1 += A.z * v.z; acc1 += A.w * v.w;
            A = fa4[2][k4];
            acc2 += A.x * v.x; acc2 += A.y * v.y; acc2 += A.z * v.z; acc2 += A.w * v.w;
        }
        const float rj = g_r[t];
        drow[0][t] = fmaxf(ra[0] + rj - 2.0f * acc0, 0.0f);
        drow[1][t] = fmaxf(ra[1] + rj - 2.0f * acc1, 0.0f);
        drow[2][t] = fmaxf(ra[2] + rj - 2.0f * acc2, 0.0f);
    }
    __syncthreads();

    // triplet phase
    float acc = 0.0f;
    int   cnt = 0;   // thread 0 only

#pragma unroll 1
    for (int m = 0; m < APB; m++) {
        const int a  = a0 + m;
        const int ya = ys[a];

        if (t == 0) npos_s = 0;
        __syncthreads();

        if (ys[t] == ya && t != a) {
            int idx = atomicAdd(&npos_s, 1);
            pos_d[idx] = drow[m][t] + MARGIN_F;
        }
        __syncthreads();

        const int np = npos_s;
        if (t == 0) cnt += np * (NN - 1 - np);

        if (ys[t] != ya) {
            const float dn = drow[m][t];
            for (int i = 0; i < np; i++) {
                float v = pos_d[i] - dn;
                acc += (v > 0.0f) ? v : 0.0f;
            }
        }
        __syncthreads();  // protect npos_s / pos_d reuse
    }

    // block reduction + global accumulate + last-block finalize
    const unsigned FULL = 0xFFFFFFFFu;
#pragma unroll
    for (int off = 16; off > 0; off >>= 1)
        acc += __shfl_down_sync(FULL, acc, off);
    const int warp = t >> 5, lane = t & 31;
    if (lane == 0) red_f[warp] = acc;
    __syncthreads();
    if (warp == 0) {
        float af = (lane < NTHR / 32) ? red_f[lane] : 0.0f;
#pragma unroll
        for (int off = 8; off > 0; off >>= 1)
            af += __shfl_down_sync(FULL, af, off);
        if (lane == 0) {
            atomicAdd(&g_total, af);
            atomicAdd(&g_count, (float)cnt);
            __threadfence();
            unsigned done = atomicAdd(&g_ctr, 1u);
            if (done == NBLK - 1) {
                float tot = atomicAdd(&g_total, 0.0f);
                float cn  = atomicAdd(&g_count, 0.0f);
                out[0] = tot / cn;
                g_total = 0.0f;
                g_count = 0.0f;
                g_ctr   = 0u;
            }
        }
    }
}

extern "C" void kernel_launch(void* const* d_in, const int* in_sizes, int n_in,
                              void* d_out, int out_size) {
    const float* feat = (const float*)d_in[0];
    // d_in[1] = logits (unused by the loss)
    const int*   yv   = (const int*)d_in[2];
    float* out = (float*)d_out;

    prep_k<<<NN / 32, 256>>>(feat);
    main_k<<<NBLK, NTHR>>>(feat, yv, out);
}

// round 5
// speedup vs baseline: 3.1633x; 1.5025x over previous
#include <cuda_runtime.h>

#define NN 384
#define DD 128
#define K4 (DD / 4)         // 32 float4 per row
#define MARGIN_F 0.2f
#define APB 3               // anchors per block
#define NBLK (NN / APB)     // 128 blocks -> single wave
#define NTHR 768            // 24 warps
#define NWARP (NTHR / 32)
#define MAXPOS 64

// Scratch (no allocations allowed)
__device__ float4 g_featT4[K4 * NN];  // [k4][j] packed transpose
__device__ float  g_total;
__device__ float  g_count;
__device__ unsigned int g_ctr;

// ---- prep: transpose only. grid (12, 2): 32 j-rows x 16 k4 per block ----
__global__ void __launch_bounds__(256) prep_k(const float* __restrict__ feat) {
    __shared__ float tile[32][68];     // stride 68 floats: conflict-free col reads
    const int t = threadIdx.x;
    const int j0 = blockIdx.x * 32;
    const int kb = blockIdx.y * 16;    // k4 base

    // coalesced load: 32 rows x 64 floats (16 float4 per row, 8 thr/row x 2)
    const int row = t >> 3;
    const int c2 = t & 7;
    const float4* src = reinterpret_cast<const float4*>(feat + (j0 + row) * DD);
#pragma unroll
    for (int i = 0; i < 2; i++) {
        const int idx = c2 * 2 + i;    // local float4 col 0..15
        *reinterpret_cast<float4*>(&tile[row][idx * 4]) = src[kb + idx];
    }
    __syncthreads();

    // coalesced store: warp w writes k4 = kb + rep*8 + w, lanes = 32 j's
    const int w = t >> 5, lane = t & 31;
#pragma unroll
    for (int rep = 0; rep < 2; rep++) {
        const int kl = rep * 8 + w;    // 0..15
        float4 v = *reinterpret_cast<const float4*>(&tile[lane][kl * 4]);
        g_featT4[(kb + kl) * NN + j0 + lane] = v;
    }
}

// ---- fused distance + triplet kernel, 768 threads ----
__global__ void __launch_bounds__(NTHR) main_k(
    const float* __restrict__ feat,
    const int*   __restrict__ y,
    float*       __restrict__ out)
{
    const int t = threadIdx.x;
    const int ab = blockIdx.x * APB;
    const int j = t % NN;              // column
    const int half = t / NN;           // 0 or 1: k-split / i-split role

    __shared__ float4 fa4[APB][K4];
    __shared__ float  part[2][4][NN];  // [half][dot0,dot1,dot2,norm][j]
    __shared__ float  drow[APB][NN];
    __shared__ int    ys[NN];
    __shared__ float  ras[APB];
    __shared__ float  pos_d[APB][MAXPOS];
    __shared__ int    wc[APB][12];
    __shared__ int    wbase[APB][12];
    __shared__ int    np_s[APB];
    __shared__ float  red_f[NWARP];

    // ---- stage labels + anchor rows ----
    if (t < NN) ys[t] = y[t];
    if (t >= NN && t < NN + APB * K4) {
        const int u = t - NN;
        const int m = u / K4, k4 = u % K4;
        fa4[m][k4] = reinterpret_cast<const float4*>(feat + (ab + m) * DD)[k4];
    }
    __syncthreads();

    // ---- split-k distance partials ----
    {
        float a0a = 0.f, a1a = 0.f, a2a = 0.f, rr = 0.f;
        const int kb = half * 16;
#pragma unroll 8
        for (int kk = 0; kk < 16; kk++) {
            const int k4 = kb + kk;
            const float4 v = g_featT4[k4 * NN + j];
            float4 A;
            A = fa4[0][k4];
            a0a += A.x * v.x; a0a += A.y * v.y; a0a += A.z * v.z; a0a += A.w * v.w;
            A = fa4[1][k4];
            a1a += A.x * v.x; a1a += A.y * v.y; a1a += A.z * v.z; a1a += A.w * v.w;
            A = fa4[2][k4];
            a2a += A.x * v.x; a2a += A.y * v.y; a2a += A.z * v.z; a2a += A.w * v.w;
            rr += v.x * v.x; rr += v.y * v.y; rr += v.z * v.z; rr += v.w * v.w;
        }
        part[half][0][j] = a0a;
        part[half][1][j] = a1a;
        part[half][2][j] = a2a;
        part[half][3][j] = rr;
    }
    __syncthreads();

    // ---- combine partials; publish anchor norms ----
    float dot0 = 0.f, dot1 = 0.f, dot2 = 0.f, rj = 0.f;
    if (t < NN) {
        dot0 = part[0][0][t] + part[1][0][t];
        dot1 = part[0][1][t] + part[1][1][t];
        dot2 = part[0][2][t] + part[1][2][t];
        rj   = part[0][3][t] + part[1][3][t];
        if (t == ab)     ras[0] = rj;
        if (t == ab + 1) ras[1] = rj;
        if (t == ab + 2) ras[2] = rj;
    }
    __syncthreads();

    // ---- d2 rows + ballot compaction counts ----
    float d2r[APB];
    bool isp[APB];
    unsigned pm[APB];
    const int w = t >> 5, lane = t & 31;
    if (t < NN) {
        const float dts[3] = {dot0, dot1, dot2};
#pragma unroll
        for (int m = 0; m < APB; m++) {
            d2r[m] = fmaxf(ras[m] + rj - 2.0f * dts[m], 0.0f);
            drow[m][t] = d2r[m];
            isp[m] = (ys[t] == ys[ab + m]) && (t != ab + m);
            pm[m] = __ballot_sync(0xFFFFFFFFu, isp[m]);
            if (lane == 0) wc[m][w] = __popc(pm[m]);
        }
    }
    __syncthreads();
    if (t < APB) {
        int s = 0;
#pragma unroll
        for (int ww = 0; ww < 12; ww++) { wbase[t][ww] = s; s += wc[t][ww]; }
        np_s[t] = s;
    }
    __syncthreads();
    if (t < NN) {
#pragma unroll
        for (int m = 0; m < APB; m++) {
            if (isp[m]) {
                const int idx = wbase[m][w] + __popc(pm[m] & ((1u << lane) - 1u));
                pos_d[m][idx] = d2r[m] + MARGIN_F;
            }
        }
    }
    __syncthreads();

    // ---- phase B: triplet sums (i-loop split across halves) ----
    float acc = 0.0f;
#pragma unroll
    for (int m = 0; m < APB; m++) {
        const int npm = np_s[m];
        if (ys[j] != ys[ab + m]) {
            const float dn = drow[m][j];
            for (int i = half; i < npm; i += 2) {
                const float v = pos_d[m][i] - dn;
                acc += (v > 0.0f) ? v : 0.0f;
            }
        }
    }

    // ---- block reduction + global accumulate + last-block finalize ----
    const unsigned FULL = 0xFFFFFFFFu;
#pragma unroll
    for (int off = 16; off > 0; off >>= 1)
        acc += __shfl_down_sync(FULL, acc, off);
    if (lane == 0) red_f[w] = acc;
    __syncthreads();
    if (w == 0) {
        float af = (lane < NWARP) ? red_f[lane] : 0.0f;
#pragma unroll
        for (int off = 16; off > 0; off >>= 1)
            af += __shfl_down_sync(FULL, af, off);
        if (lane == 0) {
            const int cnt = np_s[0] * (NN - 1 - np_s[0])
                          + np_s[1] * (NN - 1 - np_s[1])
                          + np_s[2] * (NN - 1 - np_s[2]);
            atomicAdd(&g_total, af);
            atomicAdd(&g_count, (float)cnt);
            __threadfence();
            const unsigned done = atomicAdd(&g_ctr, 1u);
            if (done == NBLK - 1) {
                const float tot = atomicAdd(&g_total, 0.0f);
                const float cn  = atomicAdd(&g_count, 0.0f);
                out[0] = tot / cn;
                g_total = 0.0f;
                g_count = 0.0f;
                g_ctr   = 0u;
            }
        }
    }
}

extern "C" void kernel_launch(void* const* d_in, const int* in_sizes, int n_in,
                              void* d_out, int out_size) {
    const float* feat = (const float*)d_in[0];
    // d_in[1] = logits (unused by the loss)
    const int*   yv   = (const int*)d_in[2];
    float* out = (float*)d_out;

    prep_k<<<dim3(NN / 32, 2), 256>>>(feat);
    main_k<<<NBLK, NTHR>>>(feat, yv, out);
}